// round 12
// baseline (speedup 1.0000x reference)
#include <cuda_runtime.h>
#include <cuda_bf16.h>
#include <cstdint>
#include <cstddef>

// ---------------------------------------------------------------------------
// Problem constants
// ---------------------------------------------------------------------------
#define BATCH   4096
#define IND     512
#define OUTD    512
#define ROWLEN  514            // P + IND
#define D2      25             // D^P
#define KPAD    12800          // IND * D2
#define NCH     200            // 64-wide K chunks, c' = ib*25 + d (ib-major)
#define TILE_M  128
#define TILE_N  128
#define STAGE_B 16384          // B tile per stage: 128 rows x 128B

// smem layout (bytes) for GEMM kernel
#define OFF_BST   0                       // B stages: 4 x 16384 = 65536
#define OFF_XF    65536                   // xf: 8 blocks x 16384 = 131072
#define OFF_KBF   196608                  // kb f32 table: 25*128*4 = 12800
#define SMEM_GEMM 209408

// Packed weight, bf16, K-permuted ib-major:
//   g_W[o][ (ib*25+d)*64 + icol ] = W[i = ib*64+icol][o][d]
__device__ __nv_bfloat16 g_W[(size_t)OUTD * KPAD];

// ---------------------------------------------------------------------------
// PTX helpers (base sm_103 ISA only)
// ---------------------------------------------------------------------------
static __device__ __forceinline__ uint32_t smem_u32(const void* p) {
    uint32_t a;
    asm("{ .reg .u64 t; cvta.to.shared.u64 t, %1; cvt.u32.u64 %0, t; }"
        : "=r"(a) : "l"(p));
    return a;
}

static __device__ __forceinline__ void cp_async16(uint32_t sdst, const void* gsrc) {
    asm volatile("{ .reg .u64 gp; cvta.to.global.u64 gp, %1;"
                 "  cp.async.cg.shared.global [%0], [gp], 16; }"
                 :: "r"(sdst), "l"(gsrc) : "memory");
}

static __device__ __forceinline__ void ldsm_x4(uint32_t* r, uint32_t addr) {
    asm volatile("ldmatrix.sync.aligned.m8n8.x4.shared.b16 {%0,%1,%2,%3}, [%4];"
                 : "=r"(r[0]), "=r"(r[1]), "=r"(r[2]), "=r"(r[3]) : "r"(addr));
}

static __device__ __forceinline__ uint32_t mul_bf16x2(uint32_t a, uint32_t b) {
    uint32_t r;
    asm("mul.rn.bf16x2 %0, %1, %2;" : "=r"(r) : "r"(a), "r"(b));
    return r;
}

static __device__ __forceinline__ void mma16816(float* c, const uint32_t* a,
                                                uint32_t b0, uint32_t b1) {
    asm volatile(
        "mma.sync.aligned.m16n8k16.row.col.f32.bf16.bf16.f32 "
        "{%0,%1,%2,%3}, {%4,%5,%6,%7}, {%8,%9}, {%0,%1,%2,%3};"
        : "+f"(c[0]), "+f"(c[1]), "+f"(c[2]), "+f"(c[3])
        : "r"(a[0]), "r"(a[1]), "r"(a[2]), "r"(a[3]), "r"(b0), "r"(b1));
}

static __device__ __forceinline__ uint16_t f2bf(float f) {
    __nv_bfloat16 h = __float2bfloat16(f);
    return *reinterpret_cast<uint16_t*>(&h);
}

// pack_W smem swizzle: XOR byte-offset bits [4:6] with (pair>>2)&7
static __device__ __forceinline__ uint32_t pk_swz(uint32_t off, int pair) {
    return off ^ (uint32_t)(((pair >> 2) & 7) << 4);
}

// ---------------------------------------------------------------------------
// Kernel 1: coalesced pack of weight (IND,OUTD,25) -> g_W (ib-major K)
// grid = (32 i-blocks of 16, 4 o-blocks of 128), block = 512
// ---------------------------------------------------------------------------
__global__ void __launch_bounds__(512, 1)
pack_W_kernel(const float* __restrict__ w)
{
    extern __shared__ char sc[];           // 3200 pairs x 32B, bank-swizzled
    const int t  = threadIdx.x;
    const int i0 = blockIdx.x * 16;
    const int o0 = blockIdx.y * 128;
    const int ib   = i0 >> 6;              // 16-block never crosses a 64-boundary
    const int icol = i0 & 63;

    // Load: per i, w[(i0+i)*512 + o0 ...] = 3200 contiguous floats, coalesced.
#pragma unroll 1
    for (int i = 0; i < 16; ++i) {
        const float4* src = reinterpret_cast<const float4*>(
            w + ((size_t)(i0 + i) * OUTD + o0) * D2);
        for (int f = t; f < 800; f += 512) {
            const float4 v = src[f];
            const int e0 = f * 4;
#pragma unroll
            for (int q = 0; q < 4; ++q) {
                const int pair = e0 + q;                 // o*25+d
                const float val = (q == 0) ? v.x : (q == 1) ? v.y
                                 : (q == 2) ? v.z : v.w;
                const uint32_t off = pk_swz((uint32_t)pair * 32 + i * 2, pair);
                *reinterpret_cast<__nv_bfloat16*>(sc + off) = __float2bfloat16(val);
            }
        }
    }
    __syncthreads();

    // Store: each (o,d) pair owns 16 bf16 = 32B = two uint4 units.
    for (int p = t; p < 128 * 25 * 2; p += 512) {
        const int pair = p >> 1;
        const int hi   = p & 1;
        const int o = pair / 25;
        const int d = pair - o * 25;
        const uint32_t off = pk_swz((uint32_t)pair * 32 + hi * 16, pair);
        const uint4 v = *reinterpret_cast<const uint4*>(sc + off);
        *reinterpret_cast<uint4*>(
            g_W + (size_t)(o0 + o) * KPAD +
            (ib * 25 + d) * 64 + icol + hi * 8) = v;
    }
}

// ---------------------------------------------------------------------------
// Kernel 2: factorized-A HMMA GEMM, ib-major K, 512 threads, 4x4 warp grid.
// 200 chunks; 2 chunks fused per epoch into an 8-PHASE software pipeline:
// one rolling 3-deep B-fragment buffer, prefetch distance 2, running ACROSS
// the chunk boundary (stage pointer switches mid-stream). One barrier/epoch.
// Bias added in an FFMA epilogue (kb f32 x smem-staged bias), then ReLU.
// grid = (32, 4), block = 512
// ---------------------------------------------------------------------------
__global__ void __launch_bounds__(512, 1)
gemm_hmma_kernel(const float* __restrict__ x, const float* __restrict__ bias,
                 float* __restrict__ out)
{
    extern __shared__ char smem[];
    const uint32_t sb = smem_u32(smem);
    const int tid  = threadIdx.x;
    const int wid  = tid >> 5;
    const int lid  = tid & 31;
    const int m0   = blockIdx.x * TILE_M;
    const int n0   = blockIdx.y * TILE_N;
    const int wm   = wid >> 2;       // 0..3  (32-row band)
    const int wn   = wid & 3;        // 0..3  (32-col band)

    // ======================= prologue: build smem state =====================
    // xf: 128 rows x 512 cols bf16 as 8 blocks [ib][row][64 cols], SW128.
    for (int f = tid; f < 128 * 256; f += 512) {      // float2 units
        const int row = f >> 8;
        const int c2  = f & 255;
        const int i   = c2 * 2;
        const float2 v = *reinterpret_cast<const float2*>(
            x + (size_t)(m0 + row) * ROWLEN + 2 + i);
        const uint32_t pk = (uint32_t)f2bf(v.x) | ((uint32_t)f2bf(v.y) << 16);
        const int ib = i >> 6;
        const int cb = i & 63;
        const uint32_t off = OFF_XF + ib * 16384 + row * 128 +
                             (((uint32_t)(cb * 2)) ^ ((uint32_t)(row & 7) << 4));
        *reinterpret_cast<uint32_t*>(smem + off) = pk;
    }
    // kb f32 table + x_treat passthrough
    if (tid < 128) {
        const float2 tt = *reinterpret_cast<const float2*>(
            x + (size_t)(m0 + tid) * ROWLEN);
        const float t0 = tt.x, t1 = tt.y;
        float u[5], v[5];
        u[0] = 1.0f; u[1] = t0; u[2] = t0 * t0;
        { float a = t0 - 0.33f; a = a > 0 ? a : 0; u[3] = a * a; }
        { float a = t0 - 0.66f; a = a > 0 ? a : 0; u[4] = a * a; }
        v[0] = 1.0f; v[1] = t1; v[2] = t1 * t1;
        { float a = t1 - 0.33f; a = a > 0 ? a : 0; v[3] = a * a; }
        { float a = t1 - 0.66f; a = a > 0 ? a : 0; v[4] = a * a; }

        float* kbf = reinterpret_cast<float*>(smem + OFF_KBF);
#pragma unroll
        for (int i = 0; i < 5; ++i)
#pragma unroll
            for (int j = 0; j < 5; ++j)
                kbf[(i * 5 + j) * 128 + tid] = u[i] * v[j];

        if (blockIdx.y == 0)
            *reinterpret_cast<float2*>(out + (size_t)(m0 + tid) * ROWLEN) = tt;
    }

    // ======================= B producer geometry ============================
    const int  pr0 = tid >> 3;                 // 0..63
    const int  pg  = tid & 7;
    const uint32_t psoff0 = (uint32_t)(pr0 * 128) +
                            ((uint32_t)(pg * 16) ^ (uint32_t)((pr0 & 7) << 4));
    const uint32_t psoff1 = (uint32_t)((pr0 + 64) * 128) +
                            ((uint32_t)(pg * 16) ^ (uint32_t)((pr0 & 7) << 4));
    const __nv_bfloat16* gB0 = g_W + (size_t)(n0 + pr0) * KPAD + pg * 8;
    const __nv_bfloat16* gB1 = g_W + (size_t)(n0 + pr0 + 64) * KPAD + pg * 8;

    // consumer geometry (ldmatrix lane addressing, SW128 swizzle)
    const int arow = wm * 32 + (lid & 15);
    const uint32_t a_sz = (uint32_t)((arow & 7) << 4);
    const uint32_t a_k  = (uint32_t)((lid >> 4) * 16);
    const int brow = wn * 32 + ((lid >> 4) << 3) + (lid & 7);
    const uint32_t b_sz = (uint32_t)((lid & 7) << 4);
    const uint32_t b_k  = (uint32_t)(((lid >> 3) & 1) * 16);

    float c[2][4][4];
#pragma unroll
    for (int mt = 0; mt < 2; ++mt)
#pragma unroll
        for (int nt = 0; nt < 4; ++nt)
#pragma unroll
            for (int i = 0; i < 4; ++i) c[mt][nt][i] = 0.0f;

    // prologue: prefetch chunks 0,1 -> stages 0,1 (one commit each)
#pragma unroll
    for (int f = 0; f < 2; ++f) {
        const uint32_t dst = sb + OFF_BST + f * STAGE_B;
        cp_async16(dst + psoff0, gB0 + (size_t)f * 64);
        cp_async16(dst + psoff1, gB1 + (size_t)f * 64);
        asm volatile("cp.async.commit_group;" ::: "memory");
    }
    __syncthreads();   // also covers xf/kbf smem population

    const float* kbf = reinterpret_cast<const float*>(smem + OFF_KBF);
    const int krow0 = wm * 32 + (lid >> 2);   // fragment row within tile (+mt*16)

    uint32_t xfA[4][2][4];   // raw xf frags [ks][mt][reg], persists across d
    uint32_t aS[2][4];       // scaled frags for current phase
    uint32_t bF[3][2][4];    // B frags, 3-deep rolling buffer (distance 2)

#define LOAD_XFA(base)                                                         \
    {   _Pragma("unroll")                                                      \
        for (int ks = 0; ks < 4; ++ks)                                         \
            _Pragma("unroll")                                                  \
            for (int mt = 0; mt < 2; ++mt)                                     \
                ldsm_x4(xfA[ks][mt], (base) + (uint32_t)(arow + mt * 16) * 128 \
                        + (((uint32_t)(ks * 32) + a_k) ^ a_sz));               \
    }

#define LOAD_B(buf, stg, kk)                                                   \
    {   const uint32_t kof = (uint32_t)((kk) * 32);                            \
        _Pragma("unroll")                                                      \
        for (int np = 0; np < 2; ++np)                                         \
            ldsm_x4(bF[buf][np], (stg) + (uint32_t)(brow + np * 16) * 128 +    \
                                 ((kof + b_k) ^ b_sz));                        \
    }

    int dcnt = 0, ibc = 0;

    // ====== main loop: 8-phase fused epochs (2 chunks), 1 barrier/epoch =====
    for (int e = 0; e < NCH; e += 2) {
        // prefetch chunks e+2, e+3 (empty commits at tail keep groups counted)
#pragma unroll
        for (int k = 2; k < 4; ++k) {
            const int f = e + k;
            if (f < NCH) {
                const uint32_t dst = sb + OFF_BST + (f & 3) * STAGE_B;
                cp_async16(dst + psoff0, gB0 + (size_t)f * 64);
                cp_async16(dst + psoff1, gB1 + (size_t)f * 64);
            }
            asm volatile("cp.async.commit_group;" ::: "memory");
        }
        asm volatile("cp.async.wait_group %0;" :: "n"(2) : "memory");

        // chunk/scale bookkeeping for both halves of the epoch
        const int d0 = dcnt, ib0 = ibc;
        int d1 = d0 + 1, ib1 = ib0;
        if (d1 == D2) { d1 = 0; ++ib1; }

        if (d0 == 0) LOAD_XFA(sb + OFF_XF + (uint32_t)ib0 * 16384);

        uint32_t kLo[2][2], kHi[2][2];
#pragma unroll
        for (int mt = 0; mt < 2; ++mt) {
            const int r = krow0 + mt * 16;
            kLo[0][mt] = (uint32_t)f2bf(kbf[d0 * 128 + r]) * 0x10001u;
            kHi[0][mt] = (uint32_t)f2bf(kbf[d0 * 128 + r + 8]) * 0x10001u;
            kLo[1][mt] = (uint32_t)f2bf(kbf[d1 * 128 + r]) * 0x10001u;
            kHi[1][mt] = (uint32_t)f2bf(kbf[d1 * 128 + r + 8]) * 0x10001u;
        }

        const uint32_t stB0 = sb + OFF_BST + (e & 3) * STAGE_B;
        const uint32_t stB1 = sb + OFF_BST + ((e + 1) & 3) * STAGE_B;

        // rolling pipeline: phases 0..7, chunk = p>>2, ks = p&3, distance-2
        LOAD_B(0, stB0, 0);
        LOAD_B(1, stB0, 1);
#pragma unroll
        for (int p = 0; p < 8; ++p) {
            const int cur = p % 3;
            if (p < 6) {
                const int q = p + 2;
                LOAD_B(q % 3, (q < 4) ? stB0 : stB1, q & 3);
            }
            const int half = p >> 2;
            const int ks   = p & 3;
            if (p == 4 && d1 == 0)     // intra-epoch ib boundary (rare)
                LOAD_XFA(sb + OFF_XF + (uint32_t)ib1 * 16384);
#pragma unroll
            for (int mt = 0; mt < 2; ++mt) {
                aS[mt][0] = mul_bf16x2(xfA[ks][mt][0], kLo[half][mt]);
                aS[mt][1] = mul_bf16x2(xfA[ks][mt][1], kHi[half][mt]);
                aS[mt][2] = mul_bf16x2(xfA[ks][mt][2], kLo[half][mt]);
                aS[mt][3] = mul_bf16x2(xfA[ks][mt][3], kHi[half][mt]);
            }
#pragma unroll
            for (int mt = 0; mt < 2; ++mt)
#pragma unroll
                for (int np = 0; np < 2; ++np) {
                    mma16816(c[mt][2 * np],     aS[mt], bF[cur][np][0], bF[cur][np][1]);
                    mma16816(c[mt][2 * np + 1], aS[mt], bF[cur][np][2], bF[cur][np][3]);
                }
        }

        dcnt = d1 + 1; ibc = ib1;
        if (dcnt == D2) { dcnt = 0; ++ibc; }

        __syncthreads();   // separates this epoch's reads from next's writes
    }

    // ================= bias epilogue: c += kb(f32) @ bias^T =================
    asm volatile("cp.async.wait_group %0;" :: "n"(0) : "memory");
    float* sbias = reinterpret_cast<float*>(smem + OFF_BST);
    {
        const float* gb = bias + (size_t)n0 * D2;
        for (int i = tid; i < 128 * D2; i += 512) sbias[i] = gb[i];
    }
    __syncthreads();

    {
        const int cb0 = wn * 32 + ((lid & 3) << 1);   // local col base
#pragma unroll 1
        for (int d = 0; d < D2; ++d) {
            float kbA[2], kbB[2];
#pragma unroll
            for (int mt = 0; mt < 2; ++mt) {
                const int r = krow0 + mt * 16;
                kbA[mt] = kbf[d * 128 + r];
                kbB[mt] = kbf[d * 128 + r + 8];
            }
#pragma unroll
            for (int nt = 0; nt < 4; ++nt) {
                const int cc = cb0 + nt * 8;
                const float b0 = sbias[cc * D2 + d];
                const float b1 = sbias[(cc + 1) * D2 + d];
#pragma unroll
                for (int mt = 0; mt < 2; ++mt) {
                    c[mt][nt][0] += kbA[mt] * b0;
                    c[mt][nt][1] += kbA[mt] * b1;
                    c[mt][nt][2] += kbB[mt] * b0;
                    c[mt][nt][3] += kbB[mt] * b1;
                }
            }
        }
    }

    // ---- fused ReLU epilogue
    {
        const int rbase = m0 + wm * 32 + (lid >> 2);
        const int cbase = n0 + wn * 32 + ((lid & 3) << 1);
#pragma unroll
        for (int mt = 0; mt < 2; ++mt) {
            const int r = rbase + mt * 16;
#pragma unroll
            for (int nt = 0; nt < 4; ++nt) {
                const int cc = cbase + nt * 8;
                float2 v0, v1;
                v0.x = fmaxf(c[mt][nt][0], 0.0f);
                v0.y = fmaxf(c[mt][nt][1], 0.0f);
                v1.x = fmaxf(c[mt][nt][2], 0.0f);
                v1.y = fmaxf(c[mt][nt][3], 0.0f);
                *reinterpret_cast<float2*>(out + (size_t)r * ROWLEN + 2 + cc) = v0;
                *reinterpret_cast<float2*>(out + (size_t)(r + 8) * ROWLEN + 2 + cc) = v1;
            }
        }
    }
}

// ---------------------------------------------------------------------------
// Launch
// ---------------------------------------------------------------------------
extern "C" void kernel_launch(void* const* d_in, const int* in_sizes, int n_in,
                              void* d_out, int out_size)
{
    (void)in_sizes; (void)n_in; (void)out_size;
    const float* x    = (const float*)d_in[0];   // (4096, 514)
    const float* w    = (const float*)d_in[1];   // (512, 512, 25)
    const float* bias = (const float*)d_in[2];   // (512, 25)
    float* out = (float*)d_out;                  // (4096, 514)

    cudaFuncSetAttribute(pack_W_kernel,
                         cudaFuncAttributeMaxDynamicSharedMemorySize, 102400);
    cudaFuncSetAttribute(gemm_hmma_kernel,
                         cudaFuncAttributeMaxDynamicSharedMemorySize, SMEM_GEMM);

    pack_W_kernel<<<dim3(32, 4), 512, 102400>>>(w);
    gemm_hmma_kernel<<<dim3(BATCH / TILE_M, OUTD / TILE_N), 512, SMEM_GEMM>>>(
        x, bias, out);
}